// round 3
// baseline (speedup 1.0000x reference)
#include <cuda_runtime.h>

#define NB_DIMS 128
#define BATCH   16384

// One warp per sample: lane L loads float4 L of each of the two gathered rows
// (128 floats = 32 float4 = one per lane), computes the partial dot, warp-reduces.
__global__ void __launch_bounds__(256) sgns_dot_kernel(
    const int*   __restrict__ vii,   // [BATCH, 2] int32 (JAX x64 disabled)
    const float* __restrict__ W,     // [NB_VECS, 128] f32
    float*       __restrict__ out)   // [BATCH] f32
{
    int gtid = blockIdx.x * blockDim.x + threadIdx.x;
    int warp = gtid >> 5;
    int lane = gtid & 31;
    if (warp >= BATCH) return;

    // Both indices with one 64-bit load (coalesced, one LDG.64 per lane-0..31,
    // all lanes of a warp read the same 8 bytes -> broadcast).
    int2 idx = __ldg(reinterpret_cast<const int2*>(vii) + warp);

    const float4* __restrict__ r0 =
        reinterpret_cast<const float4*>(W + (long long)idx.x * NB_DIMS);
    const float4* __restrict__ r1 =
        reinterpret_cast<const float4*>(W + (long long)idx.y * NB_DIMS);

    float4 a = __ldg(r0 + lane);
    float4 b = __ldg(r1 + lane);

    float s = a.x * b.x + a.y * b.y + a.z * b.z + a.w * b.w;

    #pragma unroll
    for (int o = 16; o > 0; o >>= 1)
        s += __shfl_down_sync(0xffffffffu, s, o);

    if (lane == 0) out[warp] = s;
}

extern "C" void kernel_launch(void* const* d_in, const int* in_sizes, int n_in,
                              void* d_out, int out_size)
{
    // Select by element count so input ordering can't bite us:
    // vii has BATCH*2 = 32768 elements, W has 1e6*128 = 128M elements.
    const void* p0 = d_in[0];
    const void* p1 = d_in[1];
    const int*   vii;
    const float* W;
    if (in_sizes[0] < in_sizes[1]) {
        vii = (const int*)p0;  W = (const float*)p1;
    } else {
        vii = (const int*)p1;  W = (const float*)p0;
    }
    float* out = (float*)d_out;

    const int threads = 256;                       // 8 warps/block
    const int blocks  = (BATCH * 32) / threads;    // 2048 blocks
    sgns_dot_kernel<<<blocks, threads>>>(vii, W, out);
}